// round 2
// baseline (speedup 1.0000x reference)
#include <cuda_runtime.h>

// QFD2Loss: mean_b q_b A q_b^T with A[j,k] = 1 - |j-k|/(L-1), L=64, q = D - D_pred.
//
// Closed form per sample (avoids the L x L matrix entirely):
//   qAq = S^2 - (2/(L-1)) * sum_{t=1}^{L-1} P_t * (S - P_t)
//       = S^2 - (2/63) * (S * sum P_t - sum P_t^2)
// where P_t is the inclusive prefix sum of q. Single streaming pass.
//
// Memory-bound: 134.2 MB read, 4 B write. Two-stage deterministic reduction.

#define THREADS 256
#define MAX_BLOCKS 8192

__device__ float g_partials[MAX_BLOCKS];

__global__ void __launch_bounds__(THREADS)
qfd2_main_kernel(const float* __restrict__ D,
                 const float* __restrict__ Dp,
                 int B)
{
    int row = blockIdx.x * blockDim.x + threadIdx.x;
    float val = 0.0f;

    if (row < B) {
        const float4* d4 = reinterpret_cast<const float4*>(D  + (size_t)row * 64);
        const float4* p4 = reinterpret_cast<const float4*>(Dp + (size_t)row * 64);

        float P  = 0.0f;   // running prefix sum
        float As = 0.0f;   // sum of P_t (includes t=64 term, corrected below)
        float B2 = 0.0f;   // sum of P_t^2 (same)

        #pragma unroll
        for (int i = 0; i < 16; i++) {
            float4 a = __ldg(d4 + i);
            float4 b = __ldg(p4 + i);
            float q;
            q = a.x - b.x; P += q; As += P; B2 = fmaf(P, P, B2);
            q = a.y - b.y; P += q; As += P; B2 = fmaf(P, P, B2);
            q = a.z - b.z; P += q; As += P; B2 = fmaf(P, P, B2);
            q = a.w - b.w; P += q; As += P; B2 = fmaf(P, P, B2);
        }
        float S = P;
        // accumulated t = 1..64; formula needs t = 1..63 -> drop the P_64 = S term
        As -= S;
        B2 -= S * S;
        val = S * S - (2.0f / 63.0f) * (S * As - B2);
    }

    // --- deterministic block reduction (tree) ---
    __shared__ float sm[THREADS / 32];
    #pragma unroll
    for (int o = 16; o > 0; o >>= 1)
        val += __shfl_down_sync(0xffffffff, val, o);
    if ((threadIdx.x & 31) == 0)
        sm[threadIdx.x >> 5] = val;
    __syncthreads();
    if (threadIdx.x < 32) {
        float v = (threadIdx.x < THREADS / 32) ? sm[threadIdx.x] : 0.0f;
        #pragma unroll
        for (int o = 4; o > 0; o >>= 1)
            v += __shfl_down_sync(0xffffffff, v, o);
        if (threadIdx.x == 0)
            g_partials[blockIdx.x] = v;
    }
}

__global__ void __launch_bounds__(256)
qfd2_final_kernel(float* __restrict__ out, int n_partials, float inv_B)
{
    __shared__ double sm[256];
    double s = 0.0;
    for (int i = threadIdx.x; i < n_partials; i += 256)
        s += (double)g_partials[i];
    sm[threadIdx.x] = s;
    __syncthreads();
    #pragma unroll
    for (int stride = 128; stride > 0; stride >>= 1) {
        if (threadIdx.x < stride)
            sm[threadIdx.x] += sm[threadIdx.x + stride];
        __syncthreads();
    }
    if (threadIdx.x == 0)
        out[0] = (float)(sm[0] * (double)inv_B);
}

extern "C" void kernel_launch(void* const* d_in, const int* in_sizes, int n_in,
                              void* d_out, int out_size)
{
    const float* D  = (const float*)d_in[0];
    const float* Dp = (const float*)d_in[1];
    float* out = (float*)d_out;

    const int L = 64;
    int B = in_sizes[0] / L;                 // 262144
    int blocks = (B + THREADS - 1) / THREADS; // 1024
    if (blocks > MAX_BLOCKS) blocks = MAX_BLOCKS;

    qfd2_main_kernel<<<blocks, THREADS>>>(D, Dp, B);
    qfd2_final_kernel<<<1, 256>>>(out, blocks, 1.0f / (float)B);
}

// round 4
// speedup vs baseline: 1.5255x; 1.5255x over previous
#include <cuda_runtime.h>

// QFD2Loss: mean_b q A q^T, A[j,k] = 1-|j-k|/63, L=64, q = D - D_pred.
// Closed form: qAq = S^2 - (2/63) * (S*(sumP - S) - (sumP2 - S^2)),
// P_t = inclusive prefix sums of q (t=1..64; the t=64 term is subtracted off).
//
// Warp-cooperative coalesced layout: each warp-iteration loads 512B contiguous
// from each input (one float4/lane) = 2 rows; 16 lanes per row. Prefix handled
// with a 16-lane segmented shuffle scan. Single fused kernel, deterministic
// last-block reduction (int atomic counter only; fixed-order double sum).

#define THREADS 256
#define BLOCKS 1024

__device__ float g_partials[BLOCKS];
__device__ unsigned int g_done_count = 0;

__global__ void __launch_bounds__(THREADS)
qfd2_fused_kernel(const float* __restrict__ D,
                  const float* __restrict__ Dp,
                  float* __restrict__ out, int B)
{
    const unsigned FULL = 0xffffffffu;
    const float c = 2.0f / 63.0f;
    const int lane   = threadIdx.x & 31;
    const int lane16 = lane & 15;
    const int warp_global  = (blockIdx.x * blockDim.x + threadIdx.x) >> 5;
    const int total_warps  = (gridDim.x * blockDim.x) >> 5;
    const int rp_total     = B >> 1;       // row-pairs (2 rows per warp-iter)

    const float4* D4 = reinterpret_cast<const float4*>(D);
    const float4* P4 = reinterpret_cast<const float4*>(Dp);

    float acc = 0.0f;

    #pragma unroll 2
    for (int rp = warp_global; rp < rp_total; rp += total_warps) {
        int idx = rp * 32 + lane;          // 512B contiguous per warp per array
        float4 a = __ldg(D4 + idx);
        float4 b = __ldg(P4 + idx);

        float q0 = a.x - b.x, q1 = a.y - b.y, q2 = a.z - b.z, q3 = a.w - b.w;
        // local inclusive prefix of this lane's 4 elements
        float p1 = q0, p2 = p1 + q1, p3 = p2 + q2, p4 = p3 + q3;

        // inclusive scan of lane-sums across the 16-lane row segment
        float sc = p4;
        #pragma unroll
        for (int off = 1; off < 16; off <<= 1) {
            float n = __shfl_up_sync(FULL, sc, off, 16);
            if (lane16 >= off) sc += n;
        }
        float excl = sc - p4;              // exclusive prefix before this lane
        float P1 = excl + p1, P2 = excl + p2, P3 = excl + p3, Pq = excl + p4;

        float As = (P1 + P2) + (P3 + Pq);                          // sum P_t (this lane's t's)
        float B2 = fmaf(P1, P1, fmaf(P2, P2, fmaf(P3, P3, Pq * Pq)));

        float S = __shfl_sync(FULL, sc, 15, 16);   // row total (lane 15 of segment)

        // segment-wide reduce of As, B2 (16-lane xor butterfly)
        #pragma unroll
        for (int off = 8; off >= 1; off >>= 1) {
            As += __shfl_xor_sync(FULL, As, off, 16);
            B2 += __shfl_xor_sync(FULL, B2, off, 16);
        }

        if (lane16 == 0) {
            // drop the t=64 term: sumP(1..63) = As - S, sumP2(1..63) = B2 - S^2
            acc += S * S - c * (S * (As - S) - fmaf(-S, S, B2));
        }
    }

    // ---- deterministic block reduction ----
    __shared__ float sm[THREADS / 32];
    __shared__ int is_last;
    #pragma unroll
    for (int off = 16; off > 0; off >>= 1)
        acc += __shfl_down_sync(FULL, acc, off);
    if (lane == 0) sm[threadIdx.x >> 5] = acc;
    __syncthreads();
    if (threadIdx.x < 32) {
        float v = (threadIdx.x < THREADS / 32) ? sm[threadIdx.x] : 0.0f;
        #pragma unroll
        for (int off = 4; off > 0; off >>= 1)
            v += __shfl_down_sync(FULL, v, off);
        if (threadIdx.x == 0) {
            g_partials[blockIdx.x] = v;
            __threadfence();
            unsigned old = atomicAdd(&g_done_count, 1u);
            is_last = (old == gridDim.x - 1) ? 1 : 0;
        }
    }
    __syncthreads();

    // ---- last block: fixed-order double-precision final sum (deterministic) ----
    if (is_last) {
        __shared__ double dsm[THREADS];
        double s = 0.0;
        for (int i = threadIdx.x; i < (int)gridDim.x; i += blockDim.x)
            s += (double)g_partials[i];
        dsm[threadIdx.x] = s;
        __syncthreads();
        #pragma unroll
        for (int st = THREADS / 2; st > 0; st >>= 1) {
            if (threadIdx.x < st) dsm[threadIdx.x] += dsm[threadIdx.x + st];
            __syncthreads();
        }
        if (threadIdx.x == 0) {
            out[0] = (float)(dsm[0] / (double)B);
            g_done_count = 0;              // reset for next graph replay
        }
    }
}

extern "C" void kernel_launch(void* const* d_in, const int* in_sizes, int n_in,
                              void* d_out, int out_size)
{
    const float* D  = (const float*)d_in[0];
    const float* Dp = (const float*)d_in[1];
    float* out = (float*)d_out;

    const int L = 64;
    int B = in_sizes[0] / L;               // 262144

    qfd2_fused_kernel<<<BLOCKS, THREADS>>>(D, Dp, out, B);
}